// round 3
// baseline (speedup 1.0000x reference)
#include <cuda_runtime.h>

#define NIN     64
#define NOUT    64
#define NJ      (NIN * NOUT)       // 4096
#define NKNOTS  10
#define NBASIS  6
#define BATCH_TILE 14
#define THREADS 512

// L2-resident accumulator for sum_b |spl[b, j]| + completion ticket.
// Zero-initialized at module load; the last block resets them each launch,
// so every graph replay sees zeros (deterministic).
__device__ float        g_splacc[NJ];
__device__ unsigned int g_ticket;

__global__ __launch_bounds__(THREADS, 1)
void kan_fused_kernel(const float* __restrict__ x,
                      const float* __restrict__ c_basis,
                      const float* __restrict__ c_spl,
                      const float* __restrict__ c_res,
                      const float* __restrict__ grid,
                      float* __restrict__ y_out,
                      float* __restrict__ reg_out,
                      int batch, float inv_batch)
{
    // features: [c][b_local][i], c = 0..5 basis, 6 = silu
    __shared__ __align__(16) float sfeat[7][BATCH_TILE][NIN];
    __shared__ float sy[BATCH_TILE][NOUT];
    __shared__ int   s_last;

    const int t    = threadIdx.x;
    const int lane = t & 31;     // i-pair index: i = 2*lane + ii
    const int oq   = t >> 5;     // o quad: o = oq*4 + q, q = 0..3
    const int b0   = blockIdx.x * BATCH_TILE;
    const int nbl  = min(BATCH_TILE, batch - b0);   // may be <= 0 for tail blocks

    // ---- register-resident coefficients for this thread's 8 j-values ----
    float cb[4][2][NBASIS];
    float csp[4][2], crs[4][2];
    #pragma unroll
    for (int q = 0; q < 4; q++) {
        #pragma unroll
        for (int ii = 0; ii < 2; ii++) {
            int j = (oq * 4 + q) * NIN + lane * 2 + ii;
            #pragma unroll
            for (int c = 0; c < NBASIS; c++) cb[q][ii][c] = __ldg(&c_basis[j * NBASIS + c]);
            csp[q][ii] = __ldg(&c_spl[j]);
            crs[q][ii] = __ldg(&c_res[j]);
        }
    }

    // ---- phase 1: spline basis + silu for nbl x NIN x-values ----
    for (int p = t; p < BATCH_TILE * NIN; p += THREADS) {
        int bl = p >> 6;          // local batch
        int i  = p & 63;          // input index
        int b  = b0 + bl;
        float xv = (b < batch) ? x[b * NIN + i] : 0.0f;

        float kn[NKNOTS];
        #pragma unroll
        for (int m = 0; m < NKNOTS; m++) kn[m] = __ldg(&grid[i * NKNOTS + m]);

        float bs[9];
        #pragma unroll
        for (int m = 0; m < 9; m++)
            bs[m] = (xv >= kn[m] && xv < kn[m + 1]) ? 1.0f : 0.0f;

        #pragma unroll
        for (int K = 1; K <= 3; K++) {
            #pragma unroll
            for (int m = 0; m <= 8 - K; m++) {
                float left  = (xv - kn[m]) / (kn[m + K] - kn[m]);
                float right = (kn[m + K + 1] - xv) / (kn[m + K + 1] - kn[m + 1]);
                bs[m] = left * bs[m] + right * bs[m + 1];
            }
        }
        #pragma unroll
        for (int c = 0; c < NBASIS; c++) sfeat[c][bl][i] = bs[c];
        float sig = 1.0f / (1.0f + __expf(-xv));
        sfeat[6][bl][i] = xv * sig;
    }
    __syncthreads();

    // ---- phase 2: fused spl / y / |spl| accumulation ----
    float acc[4][2];
    #pragma unroll
    for (int q = 0; q < 4; q++) { acc[q][0] = 0.0f; acc[q][1] = 0.0f; }

    #pragma unroll 1
    for (int bl = 0; bl < nbl; bl++) {
        float2 f[7];
        #pragma unroll
        for (int c = 0; c < 7; c++)
            f[c] = *(const float2*)&sfeat[c][bl][lane * 2];

        float yp[4];
        #pragma unroll
        for (int q = 0; q < 4; q++) {
            float s0 = cb[q][0][0] * f[0].x;
            float s1 = cb[q][1][0] * f[0].y;
            #pragma unroll
            for (int c = 1; c < NBASIS; c++) {
                s0 += cb[q][0][c] * f[c].x;
                s1 += cb[q][1][c] * f[c].y;
            }
            acc[q][0] += fabsf(s0);
            acc[q][1] += fabsf(s1);
            yp[q] = csp[q][0] * s0 + crs[q][0] * f[6].x
                  + csp[q][1] * s1 + crs[q][1] * f[6].y;
        }

        // reduce 4 values over 32 lanes in 14 shfl:
        // 3 butterfly steps (d=16,8,4) leave every lane with its mod-4-class
        // partial for all 4 q's; local select + 2 butterflies over class bits.
        #pragma unroll
        for (int d = 16; d >= 4; d >>= 1) {
            #pragma unroll
            for (int q = 0; q < 4; q++)
                yp[q] += __shfl_xor_sync(0xffffffffu, yp[q], d);
        }
        int qs = (lane >> 2) & 3;
        float v = (qs == 0) ? yp[0] : (qs == 1) ? yp[1] : (qs == 2) ? yp[2] : yp[3];
        v += __shfl_xor_sync(0xffffffffu, v, 1);
        v += __shfl_xor_sync(0xffffffffu, v, 2);
        if (lane < 16 && (lane & 3) == 0)
            sy[bl][oq * 4 + (lane >> 2)] = v;
    }
    __syncthreads();

    // ---- write y (coalesced) ----
    for (int p = t; p < BATCH_TILE * NOUT; p += THREADS) {
        int bl = p >> 6;
        int o  = p & 63;
        if (bl < nbl)
            y_out[(b0 + bl) * NOUT + o] = sy[bl][o] * (1.0f / NIN);
    }

    // ---- accumulate |spl| partials into L2 ----
    #pragma unroll
    for (int q = 0; q < 4; q++) {
        #pragma unroll
        for (int ii = 0; ii < 2; ii++) {
            int j = (oq * 4 + q) * NIN + lane * 2 + ii;
            atomicAdd(&g_splacc[j], acc[q][ii]);
        }
    }

    // ---- last-block-done: finalize spl_reg + reset accumulators ----
    __threadfence();
    __syncthreads();
    if (t == 0) {
        unsigned r = atomicAdd(&g_ticket, 1u);
        s_last = (r == gridDim.x - 1) ? 1 : 0;
    }
    __syncthreads();
    if (s_last) {
        for (int j = t; j < NJ; j += THREADS) {
            float v    = __ldcg(&g_splacc[j]);   // L2-coherent read of atomic results
            float norm = __ldg(&grid[j * NKNOTS + NKNOTS - 1])
                       - __ldg(&grid[j * NKNOTS]) + 1e-5f;
            reg_out[j] = v * inv_batch / norm;
            g_splacc[j] = 0.0f;                  // reset for next graph replay
        }
        __threadfence();
        __syncthreads();
        if (t == 0) atomicExch(&g_ticket, 0u);   // reset ticket for next replay
    }
}

extern "C" void kernel_launch(void* const* d_in, const int* in_sizes, int n_in,
                              void* d_out, int out_size)
{
    const float* x       = (const float*)d_in[0];
    const float* c_basis = (const float*)d_in[1];
    const float* c_spl   = (const float*)d_in[2];
    const float* c_res   = (const float*)d_in[3];
    const float* grid    = (const float*)d_in[4];

    int batch = in_sizes[0] / NIN;

    float* y_out   = (float*)d_out;                 // (batch, 64)
    float* reg_out = y_out + (size_t)batch * NOUT;  // (64, 64)

    int blocks = (batch + BATCH_TILE - 1) / BATCH_TILE;
    kan_fused_kernel<<<blocks, THREADS>>>(x, c_basis, c_spl, c_res, grid,
                                          y_out, reg_out, batch, 1.0f / (float)batch);
}